// round 6
// baseline (speedup 1.0000x reference)
#include <cuda_runtime.h>

#define SDIM 26
#define SS   676          // 26*26
#define CNUM 80
#define NCH  255          // 3*(5+80)
#define NB   32
#define BATCH 256
#define DIV  16.0f        // 416/26
#define IMG  416.0f

__device__ float g_partial[BATCH];
__device__ unsigned int g_count = 0;

__device__ __constant__ float c_anchor[9][2] = {
    {10.f,13.f},{16.f,30.f},{33.f,23.f},{30.f,61.f},{62.f,45.f},
    {59.f,119.f},{116.f,90.f},{156.f,198.f},{373.f,326.f}};

__device__ __forceinline__ float warp_sum(float v) {
#pragma unroll
    for (int o = 16; o > 0; o >>= 1) v += __shfl_down_sync(0xffffffffu, v, o);
    return v;
}

__global__ __launch_bounds__(256) void yolo_fused_kernel(
    const float* __restrict__ x,      // (B, 255, 26, 26)
    const float* __restrict__ box,    // (B, 32, 5)
    const int*   __restrict__ bidx,   // (B, 32)
    float*       __restrict__ out)
{
    const int b   = blockIdx.x;
    const int tid = threadIdx.x;
    const float* xb = x + (size_t)b * NCH * SS;

    __shared__ int   sh_base[NB];
    __shared__ int   sh_pos[NB];
    __shared__ int   sh_cls[NB];
    __shared__ float sh_wn[8];
    __shared__ float sh_wl[8];
    __shared__ float sh_scalar[3]; // boxloss, corr, ucnt
    __shared__ int   sh_islast;

    float boxloss = 0.0f;

    // ---- per-box scalar work: warp 0 (32 lanes == 32 boxes) ----
    if (tid < NB) {
        const float* bp = box + ((size_t)b * NB + tid) * 5;
        float cls = bp[0];
        float cx  = bp[1];
        float cy  = bp[2];
        float w   = bp[3];
        float h   = bp[4];
        int   ni  = bidx[(size_t)b * NB + tid];      // 3..5
        int   base = (ni - 3) * (5 + CNUM);          // 0 / 85 / 170
        int   ix  = (int)(cx / DIV);
        int   iy  = (int)(cy / DIV);
        float ax  = (cx - (float)ix * DIV) / DIV;
        float ay  = (cy - (float)iy * DIV) / DIV;
        int   pos = ix * SDIM + iy;

        sh_base[tid] = base;
        sh_pos[tid]  = pos;
        sh_cls[tid]  = (int)cls;

        const float* xc = xb + pos;
        float obj = xc[(size_t)(base + 0) * SS];
        float rax = xc[(size_t)(base + 1) * SS];
        float ray = xc[(size_t)(base + 2) * SS];
        float s3  = xc[(size_t)(base + 3) * SS];
        float s4  = xc[(size_t)(base + 4) * SS];

        float sig3 = 1.0f / (1.0f + __expf(-s3));
        float sig4 = 1.0f / (1.0f + __expf(-s4));
        float rw = c_anchor[ni][0] * __expf(4.0f * sig3 - 2.0f);
        float rh = c_anchor[ni][1] * __expf(4.0f * sig4 - 2.0f);

        // IoU
        float b1x1 = rax * DIV - rw * 0.5f, b1y1 = ray * DIV - rh * 0.5f;
        float b1x2 = rax * DIV + rw * 0.5f, b1y2 = ray * DIV + rh * 0.5f;
        float b2x1 = ax * DIV - w * 0.5f,   b2y1 = ay * DIV - h * 0.5f;
        float b2x2 = ax * DIV + w * 0.5f,   b2y2 = ay * DIV + h * 0.5f;
        float A  = (b1x2 - b1x1 + 1.0f) * (b1y2 - b1y1 + 1.0f);
        float Bt = (b2x2 - b2x1 + 1.0f) * (b2y2 - b2y1 + 1.0f);
        float CM = (fminf(b1x2, b2x2) - fmaxf(b1x1, b2x1) + 1.0f) *
                   (fminf(b1y2, b2y2) - fmaxf(b1y1, b2y1) + 1.0f);
        float r  = CM / (A + Bt - CM);
        float iou = (r < 0.0f) ? 0.0f : r;

        float d0 = obj - iou;
        float d1 = rax - ax;
        float d2 = ray - ay;
        float d3 = (rw - w) / IMG;
        float d4 = (rh - h) / IMG;
        boxloss = d0 * d0 + d1 * d1 + d2 * d2 + d3 * d3 + d4 * d4;
    }
    __syncthreads();

    // ---- unique-triple noobj mask correction: warp 0 ----
    if (tid < 32) {
        float corr = 0.0f;
        float ucnt = 0.0f;
        int key = sh_base[tid] * SS + sh_pos[tid];
        bool uniq = true;
        for (int t2 = 0; t2 < tid; ++t2) {
            if (sh_base[t2] * SS + sh_pos[t2] == key) { uniq = false; break; }
        }
        if (uniq) {
            float v = xb[key];
            corr = v * v;
            ucnt = 1.0f;
        }
        boxloss = warp_sum(boxloss);
        corr    = warp_sum(corr);
        ucnt    = warp_sum(ucnt);
        if (tid == 0) {
            sh_scalar[0] = boxloss;
            sh_scalar[1] = corr;
            sh_scalar[2] = ucnt;
        }
    }

    // ---- label MSE over 32*80 elements: all 256 threads (10 indep loads each) ----
    float lsum = 0.0f;
#pragma unroll
    for (int e = tid; e < NB * CNUM; e += 256) {
        int t = e / CNUM;
        int j = e - t * CNUM;
        float lab = xb[(size_t)(sh_base[t] + 5 + j) * SS + sh_pos[t]];
        float hot = (j == sh_cls[t]) ? 1.0f : 0.0f;
        float d = lab - hot;
        lsum += d * d;
    }

    // ---- noobj sum of squares over channels {0,85,170}: float4, all threads ----
    float nsum = 0.0f;
#pragma unroll
    for (int p = tid; p < 3 * (SS / 4); p += 256) {
        int c = p / (SS / 4);
        int o = p - c * (SS / 4);
        const float4* xv = (const float4*)(xb + (size_t)(c * 85) * SS);
        float4 v = xv[o];
        nsum += v.x * v.x + v.y * v.y + v.z * v.z + v.w * v.w;
    }

    // ---- block reduce lsum, nsum ----
    lsum = warp_sum(lsum);
    nsum = warp_sum(nsum);
    int wid = tid >> 5;
    if ((tid & 31) == 0) { sh_wl[wid] = lsum; sh_wn[wid] = nsum; }
    __syncthreads();

    if (tid == 0) {
        float lt = 0.0f, nt = 0.0f;
#pragma unroll
        for (int i = 0; i < 8; ++i) { lt += sh_wl[i]; nt += sh_wn[i]; }
        float cnt   = 3.0f * (float)SS - sh_scalar[2];
        float noobj = (nt - sh_scalar[1]) / cnt;
        float loss  = (5.0f / (float)NB) * sh_scalar[0]
                    + lt / (float)(NB * CNUM)
                    + 0.5f * noobj;
        g_partial[b] = loss;
        __threadfence();
        unsigned int ticket = atomicAdd(&g_count, 1u);
        sh_islast = (ticket == BATCH - 1) ? 1 : 0;
    }
    __syncthreads();

    // ---- last CTA: deterministic final reduction over 256 partials ----
    if (sh_islast) {
        __threadfence();   // acquire side of the ticket handoff
        float v = g_partial[tid];
        v = warp_sum(v);
        if ((tid & 31) == 0) sh_wl[tid >> 5] = v;
        __syncthreads();
        if (tid == 0) {
            float t = 0.0f;
#pragma unroll
            for (int i = 0; i < 8; ++i) t += sh_wl[i];
            out[0] = t;
            g_count = 0;   // reset for next graph replay
        }
    }
}

extern "C" void kernel_launch(void* const* d_in, const int* in_sizes, int n_in,
                              void* d_out, int out_size)
{
    const float* x    = (const float*)d_in[0];
    const float* box  = (const float*)d_in[1];
    const int*   bidx = (const int*)d_in[2];
    yolo_fused_kernel<<<BATCH, 256>>>(x, box, bidx, (float*)d_out);
}

// round 9
// speedup vs baseline: 1.2799x; 1.2799x over previous
#include <cuda_runtime.h>

#define SDIM 26
#define SS   676          // 26*26
#define CNUM 80
#define NCH  255          // 3*(5+80)
#define NB   32
#define BATCH 256
#define IPB  2            // images per block
#define DIV  16.0f        // 416/26
#define IMG  416.0f

__device__ float g_partial[BATCH];
__device__ unsigned int g_count = 0;

__device__ __constant__ float c_anchor[9][2] = {
    {10.f,13.f},{16.f,30.f},{33.f,23.f},{30.f,61.f},{62.f,45.f},
    {59.f,119.f},{116.f,90.f},{156.f,198.f},{373.f,326.f}};

__device__ __forceinline__ float warp_sum(float v) {
#pragma unroll
    for (int o = 16; o > 0; o >>= 1) v += __shfl_down_sync(0xffffffffu, v, o);
    return v;
}

__global__ __launch_bounds__(512) void yolo_fused_kernel(
    const float* __restrict__ x,      // (B, 255, 26, 26)
    const float* __restrict__ box,    // (B, 32, 5)
    const int*   __restrict__ bidx,   // (B, 32)
    float*       __restrict__ out)
{
    const int tid  = threadIdx.x;
    const int half = tid >> 8;            // which image within the block
    const int ltid = tid & 255;           // thread id within the half
    const int b    = blockIdx.x * IPB + half;
    const float* xb = x + (size_t)b * NCH * SS;

    __shared__ int   sh_off[IPB][NB];     // (base+5)*SS + pos  (label gather base)
    __shared__ int   sh_key[IPB][NB];     // base*SS + pos      (dedup key / corr addr)
    __shared__ int   sh_cls[IPB][NB];
    __shared__ float sh_wl[IPB][8];       // per-warp label partials (8 warps/half)
    __shared__ float sh_wn[IPB][8];       // per-warp noobj partials
    __shared__ float sh_scalar[IPB][3];   // boxloss, corr, ucnt
    __shared__ int   sh_islast;

    // ---- per-box scalar work: warp 0 (half 0) / warp 8 (half 1) ----
    if (ltid < NB) {
        const float* bp = box + ((size_t)b * NB + ltid) * 5;
        float cls = bp[0];
        float cx  = bp[1];
        float cy  = bp[2];
        float w   = bp[3];
        float h   = bp[4];
        int   ni  = bidx[(size_t)b * NB + ltid];     // 3..5
        int   base = (ni - 3) * (5 + CNUM);          // 0 / 85 / 170
        int   ix  = (int)(cx / DIV);
        int   iy  = (int)(cy / DIV);
        float ax  = (cx - (float)ix * DIV) / DIV;
        float ay  = (cy - (float)iy * DIV) / DIV;
        int   pos = ix * SDIM + iy;
        int   key = base * SS + pos;

        sh_key[half][ltid] = key;
        sh_off[half][ltid] = key + 5 * SS;
        sh_cls[half][ltid] = (int)cls;

        const float* xc = xb + key;
        float obj = xc[0 * SS];
        float rax = xc[1 * SS];
        float ray = xc[2 * SS];
        float s3  = xc[3 * SS];
        float s4  = xc[4 * SS];

        float sig3 = 1.0f / (1.0f + __expf(-s3));
        float sig4 = 1.0f / (1.0f + __expf(-s4));
        float rw = c_anchor[ni][0] * __expf(4.0f * sig3 - 2.0f);
        float rh = c_anchor[ni][1] * __expf(4.0f * sig4 - 2.0f);

        // IoU
        float b1x1 = rax * DIV - rw * 0.5f, b1y1 = ray * DIV - rh * 0.5f;
        float b1x2 = rax * DIV + rw * 0.5f, b1y2 = ray * DIV + rh * 0.5f;
        float b2x1 = ax * DIV - w * 0.5f,   b2y1 = ay * DIV - h * 0.5f;
        float b2x2 = ax * DIV + w * 0.5f,   b2y2 = ay * DIV + h * 0.5f;
        float A  = (b1x2 - b1x1 + 1.0f) * (b1y2 - b1y1 + 1.0f);
        float Bt = (b2x2 - b2x1 + 1.0f) * (b2y2 - b2y1 + 1.0f);
        float CM = (fminf(b1x2, b2x2) - fmaxf(b1x1, b2x1) + 1.0f) *
                   (fminf(b1y2, b2y2) - fmaxf(b1y1, b2y1) + 1.0f);
        float r  = CM / (A + Bt - CM);
        float iou = (r < 0.0f) ? 0.0f : r;

        float d0 = obj - iou;
        float d1 = rax - ax;
        float d2 = ray - ay;
        float d3 = (rw - w) / IMG;
        float d4 = (rh - h) / IMG;
        float boxloss = d0 * d0 + d1 * d1 + d2 * d2 + d3 * d3 + d4 * d4;

        __syncwarp();   // sh_key filled by this warp, read below by this warp

        // ---- unique-triple noobj mask correction (warp-local dedup) ----
        float corr = 0.0f;
        float ucnt = 0.0f;
        bool uniq = true;
        for (int t2 = 0; t2 < ltid; ++t2) {
            if (sh_key[half][t2] == key) { uniq = false; break; }
        }
        if (uniq) {
            float v = xb[key];
            corr = v * v;
            ucnt = 1.0f;
        }
        boxloss = warp_sum(boxloss);
        corr    = warp_sum(corr);
        ucnt    = warp_sum(ucnt);
        if (ltid == 0) {
            sh_scalar[half][0] = boxloss;
            sh_scalar[half][1] = corr;
            sh_scalar[half][2] = ucnt;
        }
    }
    __syncthreads();

    // ---- label MSE over 32*80 elements: 256 threads per half ----
    float lsum = 0.0f;
#pragma unroll
    for (int e = ltid; e < NB * CNUM; e += 256) {
        int t = e / CNUM;
        int j = e - t * CNUM;
        float lab = xb[(size_t)(sh_off[half][t] + j * SS)];
        float hot = (j == sh_cls[half][t]) ? 1.0f : 0.0f;
        float d = lab - hot;
        lsum += d * d;
    }

    // ---- noobj sum of squares over channels {0,85,170}: float4 ----
    float nsum = 0.0f;
#pragma unroll
    for (int p = ltid; p < 3 * (SS / 4); p += 256) {
        int c = p / (SS / 4);
        int o = p - c * (SS / 4);
        const float4* xv = (const float4*)(xb + (size_t)(c * 85) * SS);
        float4 v = xv[o];
        nsum += v.x * v.x + v.y * v.y + v.z * v.z + v.w * v.w;
    }

    // ---- per-half block reduce ----
    lsum = warp_sum(lsum);
    nsum = warp_sum(nsum);
    int lwid = ltid >> 5;
    if ((ltid & 31) == 0) { sh_wl[half][lwid] = lsum; sh_wn[half][lwid] = nsum; }
    __syncthreads();

    if (ltid == 0) {
        float lt = 0.0f, nt = 0.0f;
#pragma unroll
        for (int i = 0; i < 8; ++i) { lt += sh_wl[half][i]; nt += sh_wn[half][i]; }
        float cnt   = 3.0f * (float)SS - sh_scalar[half][2];
        float noobj = (nt - sh_scalar[half][1]) / cnt;
        float loss  = (5.0f / (float)NB) * sh_scalar[half][0]
                    + lt / (float)(NB * CNUM)
                    + 0.5f * noobj;
        g_partial[b] = loss;
        __threadfence();   // release: make g_partial[b] device-visible
    }
    __syncthreads();

    if (tid == 0) {
        unsigned int ticket = atomicAdd(&g_count, 1u);
        sh_islast = (ticket == (BATCH / IPB) - 1) ? 1 : 0;
    }
    __syncthreads();

    // ---- last CTA: deterministic final reduction over 256 partials ----
    if (sh_islast) {
        if (tid < 256) {
            __threadfence();   // acquire side
            float v = g_partial[tid];
            v = warp_sum(v);
            if ((tid & 31) == 0) sh_wl[0][tid >> 5] = v;
        }
        __syncthreads();
        if (tid == 0) {
            float t = 0.0f;
#pragma unroll
            for (int i = 0; i < 8; ++i) t += sh_wl[0][i];
            out[0] = t;
            g_count = 0;   // reset for next graph replay
        }
    }
}

extern "C" void kernel_launch(void* const* d_in, const int* in_sizes, int n_in,
                              void* d_out, int out_size)
{
    const float* x    = (const float*)d_in[0];
    const float* box  = (const float*)d_in[1];
    const int*   bidx = (const int*)d_in[2];
    yolo_fused_kernel<<<BATCH / IPB, 512>>>(x, box, bidx, (float*)d_out);
}

// round 11
// speedup vs baseline: 1.3409x; 1.0476x over previous
#include <cuda_runtime.h>

#define SDIM 26
#define SS   676          // 26*26
#define CNUM 80
#define NCH  255          // 3*(5+80)
#define NB   32
#define BATCH 256
#define IPB  2            // images per block
#define DIV  16.0f        // 416/26
#define IMG  416.0f

__device__ float g_partial[BATCH];
__device__ unsigned int g_count = 0;

__device__ __constant__ float c_anchor[9][2] = {
    {10.f,13.f},{16.f,30.f},{33.f,23.f},{30.f,61.f},{62.f,45.f},
    {59.f,119.f},{116.f,90.f},{156.f,198.f},{373.f,326.f}};

__device__ __forceinline__ float warp_sum(float v) {
#pragma unroll
    for (int o = 16; o > 0; o >>= 1) v += __shfl_down_sync(0xffffffffu, v, o);
    return v;
}

__global__ __launch_bounds__(512) void yolo_fused_kernel(
    const float* __restrict__ x,      // (B, 255, 26, 26)
    const float* __restrict__ box,    // (B, 32, 5)
    const int*   __restrict__ bidx,   // (B, 32)
    float*       __restrict__ out)
{
    const int tid  = threadIdx.x;
    const int half = tid >> 8;            // which image within the block
    const int ltid = tid & 255;           // thread id within the half
    const int b    = blockIdx.x * IPB + half;
    const float* xb = x + (size_t)b * NCH * SS;

    __shared__ int   sh_off[IPB][NB];     // (base+5)*SS + pos  (label gather base)
    __shared__ int   sh_key[IPB][NB];     // base*SS + pos      (dedup key / corr addr)
    __shared__ int   sh_cls[IPB][NB];
    __shared__ float sh_wl[IPB][8];       // per-warp label partials (8 warps/half)
    __shared__ float sh_wn[IPB][8];       // per-warp noobj partials
    __shared__ float sh_scalar[IPB][3];   // boxloss, corr, ucnt
    __shared__ int   sh_islast;

    // ---- per-box scalar work: warp 0 (half 0) / warp 8 (half 1) ----
    if (ltid < NB) {
        const float* bp = box + ((size_t)b * NB + ltid) * 5;
        float cls = bp[0];
        float cx  = bp[1];
        float cy  = bp[2];
        float w   = bp[3];
        float h   = bp[4];
        int   ni  = bidx[(size_t)b * NB + ltid];     // 3..5
        int   base = (ni - 3) * (5 + CNUM);          // 0 / 85 / 170
        int   ix  = (int)(cx / DIV);
        int   iy  = (int)(cy / DIV);
        float ax  = (cx - (float)ix * DIV) / DIV;
        float ay  = (cy - (float)iy * DIV) / DIV;
        int   pos = ix * SDIM + iy;
        int   key = base * SS + pos;

        sh_key[half][ltid] = key;
        sh_off[half][ltid] = key + 5 * SS;
        sh_cls[half][ltid] = (int)cls;

        const float* xc = xb + key;
        float obj = xc[0 * SS];
        float rax = xc[1 * SS];
        float ray = xc[2 * SS];
        float s3  = xc[3 * SS];
        float s4  = xc[4 * SS];

        float sig3 = 1.0f / (1.0f + __expf(-s3));
        float sig4 = 1.0f / (1.0f + __expf(-s4));
        float rw = c_anchor[ni][0] * __expf(4.0f * sig3 - 2.0f);
        float rh = c_anchor[ni][1] * __expf(4.0f * sig4 - 2.0f);

        // IoU
        float b1x1 = rax * DIV - rw * 0.5f, b1y1 = ray * DIV - rh * 0.5f;
        float b1x2 = rax * DIV + rw * 0.5f, b1y2 = ray * DIV + rh * 0.5f;
        float b2x1 = ax * DIV - w * 0.5f,   b2y1 = ay * DIV - h * 0.5f;
        float b2x2 = ax * DIV + w * 0.5f,   b2y2 = ay * DIV + h * 0.5f;
        float A  = (b1x2 - b1x1 + 1.0f) * (b1y2 - b1y1 + 1.0f);
        float Bt = (b2x2 - b2x1 + 1.0f) * (b2y2 - b2y1 + 1.0f);
        float CM = (fminf(b1x2, b2x2) - fmaxf(b1x1, b2x1) + 1.0f) *
                   (fminf(b1y2, b2y2) - fmaxf(b1y1, b2y1) + 1.0f);
        float r  = CM / (A + Bt - CM);
        float iou = (r < 0.0f) ? 0.0f : r;

        float d0 = obj - iou;
        float d1 = rax - ax;
        float d2 = ray - ay;
        float d3 = (rw - w) / IMG;
        float d4 = (rh - h) / IMG;
        float boxloss = d0 * d0 + d1 * d1 + d2 * d2 + d3 * d3 + d4 * d4;

        __syncwarp();   // sh_key filled by this warp, read below by this warp

        // ---- unique-triple noobj mask correction (warp-local dedup) ----
        float corr = 0.0f;
        float ucnt = 0.0f;
        bool uniq = true;
        for (int t2 = 0; t2 < ltid; ++t2) {
            if (sh_key[half][t2] == key) { uniq = false; break; }
        }
        if (uniq) {
            float v = xb[key];
            corr = v * v;
            ucnt = 1.0f;
        }
        boxloss = warp_sum(boxloss);
        corr    = warp_sum(corr);
        ucnt    = warp_sum(ucnt);
        if (ltid == 0) {
            sh_scalar[half][0] = boxloss;
            sh_scalar[half][1] = corr;
            sh_scalar[half][2] = ucnt;
        }
    }
    __syncthreads();

    // ---- label MSE over 32*80 elements: 256 threads per half ----
    float lsum = 0.0f;
#pragma unroll
    for (int e = ltid; e < NB * CNUM; e += 256) {
        int t = e / CNUM;
        int j = e - t * CNUM;
        float lab = xb[(size_t)(sh_off[half][t] + j * SS)];
        float hot = (j == sh_cls[half][t]) ? 1.0f : 0.0f;
        float d = lab - hot;
        lsum += d * d;
    }

    // ---- noobj sum of squares over channels {0,85,170}: float4 ----
    float nsum = 0.0f;
#pragma unroll
    for (int p = ltid; p < 3 * (SS / 4); p += 256) {
        int c = p / (SS / 4);
        int o = p - c * (SS / 4);
        const float4* xv = (const float4*)(xb + (size_t)(c * 85) * SS);
        float4 v = xv[o];
        nsum += v.x * v.x + v.y * v.y + v.z * v.z + v.w * v.w;
    }

    // ---- per-half block reduce ----
    lsum = warp_sum(lsum);
    nsum = warp_sum(nsum);
    int lwid = ltid >> 5;
    if ((ltid & 31) == 0) { sh_wl[half][lwid] = lsum; sh_wn[half][lwid] = nsum; }
    __syncthreads();

    if (ltid == 0) {
        float lt = 0.0f, nt = 0.0f;
#pragma unroll
        for (int i = 0; i < 8; ++i) { lt += sh_wl[half][i]; nt += sh_wn[half][i]; }
        float cnt   = 3.0f * (float)SS - sh_scalar[half][2];
        float noobj = (nt - sh_scalar[half][1]) / cnt;
        float loss  = (5.0f / (float)NB) * sh_scalar[half][0]
                    + lt / (float)(NB * CNUM)
                    + 0.5f * noobj;
        g_partial[b] = loss;
        __threadfence();   // release: make g_partial[b] device-visible
    }
    __syncthreads();

    if (tid == 0) {
        unsigned int ticket = atomicAdd(&g_count, 1u);
        sh_islast = (ticket == (BATCH / IPB) - 1) ? 1 : 0;
    }
    __syncthreads();

    // ---- last CTA: deterministic final reduction over 256 partials ----
    if (sh_islast) {
        if (tid < 256) {
            __threadfence();   // acquire side
            float v = g_partial[tid];
            v = warp_sum(v);
            if ((tid & 31) == 0) sh_wl[0][tid >> 5] = v;
        }
        __syncthreads();
        if (tid == 0) {
            float t = 0.0f;
#pragma unroll
            for (int i = 0; i < 8; ++i) t += sh_wl[0][i];
            out[0] = t;
            g_count = 0;   // reset for next graph replay
        }
    }
}

extern "C" void kernel_launch(void* const* d_in, const int* in_sizes, int n_in,
                              void* d_out, int out_size)
{
    const float* x    = (const float*)d_in[0];
    const float* box  = (const float*)d_in[1];
    const int*   bidx = (const int*)d_in[2];
    yolo_fused_kernel<<<BATCH / IPB, 512>>>(x, box, bidx, (float*)d_out);
}